// round 14
// baseline (speedup 1.0000x reference)
#include <cuda_runtime.h>
#include <cstdint>

#define B_DIM    8
#define C_OUT    64
#define NK       7
#define GROUP_IN 4
#define C_IN     1792              // 64*4*7
#define L_DIM    4096
#define TILE     512
#define HALO     16                // covers |shift| <= 15
#define ROWW     (TILE + 2*HALO)   // 544 floats per staged row
#define ROWB     (ROWW * 4)        // 2176 bytes per staged row
#define NCH      (GROUP_IN * NK)   // 28 channels per c_out
#define QROWS    7                 // rows per quarter slot
#define QBUFB    (QROWS * ROWB)    // 15232 bytes per quarter slot
#define RING     3
#define THREADS  256
#define CTAS_SM  4
#define GRID     (152 * CTAS_SM)   // 608 persistent CTAs
#define NTILES   (B_DIM * C_OUT * (L_DIM / TILE))   // 4096

// --- TMA bulk 1D: global -> shared, mbarrier transaction-counted ---
__device__ __forceinline__ void bulk_g2s(uint32_t dst, const void* src,
                                         unsigned bytes, uint32_t mbar) {
    asm volatile(
        "cp.async.bulk.shared::cluster.global.mbarrier::complete_tx::bytes "
        "[%0], [%1], %2, [%3];"
        :: "r"(dst), "l"(src), "r"(bytes), "r"(mbar) : "memory");
}
__device__ __forceinline__ void mbar_init(uint32_t mbar, unsigned cnt) {
    asm volatile("mbarrier.init.shared.b64 [%0], %1;" :: "r"(mbar), "r"(cnt) : "memory");
}
__device__ __forceinline__ void mbar_arrive_expect(uint32_t mbar, unsigned bytes) {
    asm volatile("mbarrier.arrive.expect_tx.shared.b64 _, [%0], %1;"
                 :: "r"(mbar), "r"(bytes) : "memory");
}
__device__ __forceinline__ void mbar_arrive(uint32_t mbar) {
    asm volatile("mbarrier.arrive.shared.b64 _, [%0];" :: "r"(mbar) : "memory");
}
__device__ __forceinline__ void mbar_wait(uint32_t mbar, unsigned ph) {
    asm volatile(
        "{\n\t.reg .pred P;\n\t"
        "LAB_%=:\n\t"
        "mbarrier.try_wait.parity.acquire.cta.shared::cta.b64 P, [%0], %1, 0x989680;\n\t"
        "@P bra.uni DONE_%=;\n\t"
        "bra.uni LAB_%=;\n\t"
        "DONE_%=:\n\t}"
        :: "r"(mbar), "r"(ph) : "memory");
}

__global__ __launch_bounds__(THREADS, CTAS_SM) void addshift_kernel(
    const float* __restrict__ x,
    const int*   __restrict__ si1,
    const int*   __restrict__ si2,
    const int*   __restrict__ si3,
    float*       __restrict__ out)
{
    extern __shared__ float sm[];                 // ring of 3 quarter-buffers
    __shared__ unsigned tab[C_OUT * NCH];         // packed per-(co,lc) offsets
    __shared__ int crel_s[NCH];                   // channel elem-offset per local row
    __shared__ __align__(8) unsigned long long mbar_s[2 * RING]; // tmb[3], cmb[3]

    const int tid = threadIdx.x;
    const uint32_t sm_base  = (uint32_t)__cvta_generic_to_shared(sm);
    const uint32_t tmb_base = (uint32_t)__cvta_generic_to_shared(&mbar_s[0]);
    const uint32_t cmb_base = (uint32_t)__cvta_generic_to_shared(&mbar_s[RING]);

    // ---- one-time tables ----
    if (tid < NCH)
        crel_s[tid] = ((tid / NK) * (C_OUT * NK) + tid % NK) * L_DIM;
    for (int c = tid; c < C_IN; c += THREADS) {
        int g  = c / (C_OUT * NK);
        int r  = c - g * (C_OUT * NK);
        int co = r / NK;
        int k  = r - co * NK;
        int lc = g * NK + k;
        unsigned o1 = 4u + 20u * (unsigned)(si1[c] % NK);
        unsigned o2 = 4u + 20u * (unsigned)(si2[c] % NK);
        unsigned o3 = 4u + 20u * (unsigned)(si3[c] % NK);
        tab[co * NCH + lc] = o1 | (o2 << 8) | (o3 << 16);
    }
    if (tid == 0) {
        #pragma unroll
        for (int s = 0; s < RING; ++s) {
            mbar_init(tmb_base + 8u * s, 32);      // warp-0 lanes
            mbar_init(cmb_base + 8u * s, THREADS); // all consumers
        }
    }
    __syncthreads();   // tables + mbarrier init visible; last bar.sync in kernel

    const unsigned OSZ = (unsigned)B_DIM * C_OUT * L_DIM;   // one output tensor

    // ---- stage quarter q of tile w into ring slot s (warp 0 only) ----
    auto stage = [&](int w, int q, unsigned s) {
        const int b   = w >> 9;
        const int rem = w & 511;
        const int co  = rem >> 3;
        const int tx  = rem & 7;
        const bool front = (tx == 0);
        const bool back  = (tx == 7);
        const uint32_t slotb = sm_base + s * (unsigned)QBUFB;
        // zero the 16-float OOB halo (bytes disjoint from the bulk copy)
        if (front | back) {
            uint32_t zb = slotb + (front ? 0u : (unsigned)((TILE + HALO) * 4));
            if (tid < QROWS * 4) {                 // 28 float4 chunks
                uint32_t a = zb + (unsigned)(tid >> 2) * ROWB
                           + (unsigned)(tid & 3) * 16u;
                asm volatile("st.shared.v4.b32 [%0], {%1,%1,%1,%1};"
                             :: "r"(a), "r"(0) : "memory");
            }
        }
        const unsigned sz = (front | back) ? (ROWB - 64u) : (unsigned)ROWB;
        if (tid == 0) mbar_arrive_expect(tmb_base + 8u * s, QROWS * sz);
        else          mbar_arrive(tmb_base + 8u * s);
        if (tid < QROWS) {
            const int gstart = (tx << 9) - HALO;
            const float* src = x + ((size_t)b * C_IN + (size_t)co * NK) * L_DIM
                             + crel_s[q * QROWS + tid] + gstart
                             + (front ? HALO : 0);
            bulk_g2s(slotb + (uint32_t)tid * ROWB + (front ? 64u : 0u), src, sz,
                     tmb_base + 8u * s);
        }
    };

    // ---- prologue: warp 0 stages quarters 0,1 of first tile (lookahead 2) ----
    int w = blockIdx.x;
    if (w < NTILES && tid < 32) { stage(w, 0, 0); stage(w, 1, 1); }

    unsigned sp = 0;                 // stream position of next consumed quarter
    unsigned tph = 0, cph = 0;       // per-slot phase bits
    const char* smc = (const char*)sm + (unsigned)tid * 4u;

    while (w < NTILES) {
        const int b   = w >> 9;
        const int rem = w & 511;
        const int co  = rem >> 3;
        const int tx  = rem & 7;

        float a0 = 0.f, a1 = 0.f, a2 = 0.f, a3 = 0.f, a4 = 0.f, a5 = 0.f;

        #pragma unroll
        for (int q = 0; q < 4; ++q) {
            // stage stream position sp+2 (lookahead) from warp 0
            {
                const int qa = q + 2;
                const int w2 = w + (qa >> 2) * GRID;
                if (w2 < NTILES && tid < 32) {
                    const unsigned s2 = (unsigned)((sp + 2) % RING);
                    if (sp + 2 >= RING) {
                        mbar_wait(cmb_base + 8u * s2, (cph >> s2) & 1u);
                        cph ^= 1u << s2;
                    }
                    stage(w2, qa & 3, s2);
                }
            }
            // consume quarter q from slot sp%RING
            const unsigned s = (unsigned)(sp % RING);
            mbar_wait(tmb_base + 8u * s, (tph >> s) & 1u); tph ^= 1u << s;
            const unsigned* tp = tab + co * NCH + q * QROWS;
            const char* smb = smc + s * (unsigned)QBUFB;
            #pragma unroll
            for (int j = 0; j < QROWS; ++j) {
                unsigned p = tp[j];                   // one LDS.32 broadcast
                const char* r0 = smb + j * ROWB;
                unsigned e1 = p & 255u;
                unsigned e2 = (p >> 8) & 255u;
                unsigned e3 = p >> 16;
                a0 += *(const float*)(r0 + e1);
                a1 += *(const float*)(r0 + e1 + 1024);
                a2 += *(const float*)(r0 + e2);
                a3 += *(const float*)(r0 + e2 + 1024);
                a4 += *(const float*)(r0 + e3);
                a5 += *(const float*)(r0 + e3 + 1024);
            }
            mbar_arrive(cmb_base + 8u * s);
            ++sp;
        }

        const unsigned ob = ((unsigned)(b * C_OUT + co)) * L_DIM + (tx << 9) + tid;
        out[ob]                 = a0;
        out[ob + 256]           = a1;
        out[ob + OSZ]           = a2;
        out[ob + OSZ + 256]     = a3;
        out[ob + 2 * OSZ]       = a4;
        out[ob + 2 * OSZ + 256] = a5;

        w += GRID;
    }
}

extern "C" void kernel_launch(void* const* d_in, const int* in_sizes, int n_in,
                              void* d_out, int out_size) {
    const float* x   = (const float*)d_in[0];
    const int*   si1 = (const int*)d_in[1];
    const int*   si2 = (const int*)d_in[2];
    const int*   si3 = (const int*)d_in[3];
    float* out = (float*)d_out;

    const int smem_bytes = RING * QBUFB;      // 45696
    cudaFuncSetAttribute(addshift_kernel,
                         cudaFuncAttributeMaxDynamicSharedMemorySize, smem_bytes);

    addshift_kernel<<<GRID, THREADS, smem_bytes>>>(x, si1, si2, si3, out);
}

// round 15
// speedup vs baseline: 1.0197x; 1.0197x over previous
#include <cuda_runtime.h>
#include <cstdint>

#define B_DIM    8
#define C_OUT    64
#define NK       7
#define GROUP_IN 4
#define C_IN     1792              // 64*4*7
#define L_DIM    4096
#define TILE     512
#define HALO     16                // covers |shift| <= 15
#define ROWW     (TILE + 2*HALO)   // 544 floats per staged row
#define ROWB     (ROWW * 4)        // 2176 bytes per staged row
#define NCH      (GROUP_IN * NK)   // 28 channels per c_out
#define QROWS    7                 // rows per quarter slot
#define QBUFB    (QROWS * ROWB)    // 15232 bytes per quarter slot
#define RING     3
#define THREADS  256
#define CTAS_SM  4
#define GRID     (152 * CTAS_SM)   // 608 persistent CTAs
#define NTILES   (B_DIM * C_OUT * (L_DIM / TILE))   // 4096

__device__ int g_ctr;                         // dynamic tile queue head
__global__ void reset_kernel() { g_ctr = 0; }

// --- TMA bulk 1D: global -> shared, mbarrier transaction-counted ---
__device__ __forceinline__ void bulk_g2s(uint32_t dst, const void* src,
                                         unsigned bytes, uint32_t mbar) {
    asm volatile(
        "cp.async.bulk.shared::cluster.global.mbarrier::complete_tx::bytes "
        "[%0], [%1], %2, [%3];"
        :: "r"(dst), "l"(src), "r"(bytes), "r"(mbar) : "memory");
}
__device__ __forceinline__ void mbar_init(uint32_t mbar, unsigned cnt) {
    asm volatile("mbarrier.init.shared.b64 [%0], %1;" :: "r"(mbar), "r"(cnt) : "memory");
}
__device__ __forceinline__ void mbar_arrive_expect(uint32_t mbar, unsigned bytes) {
    asm volatile("mbarrier.arrive.expect_tx.shared.b64 _, [%0], %1;"
                 :: "r"(mbar), "r"(bytes) : "memory");
}
__device__ __forceinline__ void mbar_arrive(uint32_t mbar) {
    asm volatile("mbarrier.arrive.shared.b64 _, [%0];" :: "r"(mbar) : "memory");
}
__device__ __forceinline__ void mbar_wait(uint32_t mbar, unsigned ph) {
    asm volatile(
        "{\n\t.reg .pred P;\n\t"
        "LAB_%=:\n\t"
        "mbarrier.try_wait.parity.acquire.cta.shared::cta.b64 P, [%0], %1, 0x989680;\n\t"
        "@P bra.uni DONE_%=;\n\t"
        "bra.uni LAB_%=;\n\t"
        "DONE_%=:\n\t}"
        :: "r"(mbar), "r"(ph) : "memory");
}

__global__ __launch_bounds__(THREADS, CTAS_SM) void addshift_kernel(
    const float* __restrict__ x,
    const int*   __restrict__ si1,
    const int*   __restrict__ si2,
    const int*   __restrict__ si3,
    float*       __restrict__ out)
{
    extern __shared__ float sm[];                 // ring of 3 quarter-buffers
    __shared__ unsigned tab[C_OUT * NCH];         // packed per-(co,lc) offsets
    __shared__ int crel_s[NCH];                   // channel elem-offset per local row
    __shared__ int wq[2];                         // next-tile id, tile-parity buffered
    __shared__ int w0_s;
    __shared__ __align__(8) unsigned long long mbar_s[2 * RING]; // tmb[3], cmb[3]

    const int tid = threadIdx.x;
    const uint32_t sm_base  = (uint32_t)__cvta_generic_to_shared(sm);
    const uint32_t tmb_base = (uint32_t)__cvta_generic_to_shared(&mbar_s[0]);
    const uint32_t cmb_base = (uint32_t)__cvta_generic_to_shared(&mbar_s[RING]);

    // ---- one-time tables ----
    if (tid < NCH)
        crel_s[tid] = ((tid / NK) * (C_OUT * NK) + tid % NK) * L_DIM;
    for (int c = tid; c < C_IN; c += THREADS) {
        int g  = c / (C_OUT * NK);
        int r  = c - g * (C_OUT * NK);
        int co = r / NK;
        int k  = r - co * NK;
        int lc = g * NK + k;
        unsigned o1 = 4u + 20u * (unsigned)(si1[c] % NK);
        unsigned o2 = 4u + 20u * (unsigned)(si2[c] % NK);
        unsigned o3 = 4u + 20u * (unsigned)(si3[c] % NK);
        tab[co * NCH + lc] = o1 | (o2 << 8) | (o3 << 16);
    }
    if (tid == 0) {
        #pragma unroll
        for (int s = 0; s < RING; ++s) {
            mbar_init(tmb_base + 8u * s, 32);      // warp-0 lanes
            mbar_init(cmb_base + 8u * s, THREADS); // all consumers
        }
        w0_s = atomicAdd(&g_ctr, 1);               // first tile for this CTA
    }
    __syncthreads();   // tables + mbarriers + w0 visible; last bar.sync in kernel

    int w = w0_s;
    const unsigned OSZ = (unsigned)B_DIM * C_OUT * L_DIM;   // one output tensor

    // ---- stage quarter q of tile w_ into ring slot s (warp 0 only) ----
    auto stage = [&](int w_, int q, unsigned s) {
        const int b   = w_ >> 9;
        const int rem = w_ & 511;
        const int co  = rem >> 3;
        const int tx  = rem & 7;
        const bool front = (tx == 0);
        const bool back  = (tx == 7);
        const uint32_t slotb = sm_base + s * (unsigned)QBUFB;
        if (front | back) {                        // zero 16-float OOB halo
            uint32_t zb = slotb + (front ? 0u : (unsigned)((TILE + HALO) * 4));
            if (tid < QROWS * 4) {                 // 28 float4 chunks
                uint32_t a = zb + (unsigned)(tid >> 2) * ROWB
                           + (unsigned)(tid & 3) * 16u;
                asm volatile("st.shared.v4.b32 [%0], {%1,%1,%1,%1};"
                             :: "r"(a), "r"(0) : "memory");
            }
        }
        const unsigned sz = (front | back) ? (ROWB - 64u) : (unsigned)ROWB;
        if (tid == 0) mbar_arrive_expect(tmb_base + 8u * s, QROWS * sz);
        else          mbar_arrive(tmb_base + 8u * s);
        if (tid < QROWS) {
            const int gstart = (tx << 9) - HALO;
            const float* src = x + ((size_t)b * C_IN + (size_t)co * NK) * L_DIM
                             + crel_s[q * QROWS + tid] + gstart
                             + (front ? HALO : 0);
            bulk_g2s(slotb + (uint32_t)tid * ROWB + (front ? 64u : 0u), src, sz,
                     tmb_base + 8u * s);
        }
    };

    // ---- prologue: warp 0 stages quarters 0,1 of first tile ----
    if (w < NTILES && tid < 32) { stage(w, 0, 0); stage(w, 1, 1); }

    unsigned stq = 2;                // next stream position to stage (warp 0)
    unsigned csq = 0;                // next stream position to consume
    unsigned tph = 0, cph = 0;       // per-slot phase bits
    int pb = 0;                      // tile parity (for wq buffering)
    const char* smc = (const char*)sm + (unsigned)tid * 4u;

    while (w < NTILES) {
        const int b   = w >> 9;
        const int rem = w & 511;
        const int co  = rem >> 3;
        const int tx  = rem & 7;
        int wn = NTILES;

        float a0 = 0.f, a1 = 0.f, a2 = 0.f, a3 = 0.f, a4 = 0.f, a5 = 0.f;

        #pragma unroll
        for (int q = 0; q < 4; ++q) {
            if (tid < 32) {
                if (q == 0) {
                    // fetch next tile id; publish before this iteration's arrives
                    if (tid == 0) { wn = atomicAdd(&g_ctr, 1); wq[pb ^ 1] = wn; }
                    wn = __shfl_sync(0xffffffffu, wn, 0);
                }
                // stage stream position stq: quarters 2,3 of w then 0,1 of wn
                const int tgt_w = (q < 2) ? w : wn;
                const int tgt_q = (q < 2) ? (q + 2) : (q - 2);
                if (tgt_w < NTILES) {
                    const unsigned s2 = stq % RING;
                    if (stq >= RING) {
                        mbar_wait(cmb_base + 8u * s2, (cph >> s2) & 1u);
                        cph ^= 1u << s2;
                    }
                    stage(tgt_w, tgt_q, s2);
                }
                ++stq;
            }
            // consume quarter q from slot csq%RING
            const unsigned s = csq % RING;
            mbar_wait(tmb_base + 8u * s, (tph >> s) & 1u); tph ^= 1u << s;
            const unsigned* tp = tab + co * NCH + q * QROWS;
            const char* smb = smc + s * (unsigned)QBUFB;
            #pragma unroll
            for (int j = 0; j < QROWS; ++j) {
                unsigned p = tp[j];                   // one LDS.32 broadcast
                const char* r0 = smb + j * ROWB;
                unsigned e1 = p & 255u;
                unsigned e2 = (p >> 8) & 255u;
                unsigned e3 = p >> 16;
                a0 += *(const float*)(r0 + e1);
                a1 += *(const float*)(r0 + e1 + 1024);
                a2 += *(const float*)(r0 + e2);
                a3 += *(const float*)(r0 + e2 + 1024);
                a4 += *(const float*)(r0 + e3);
                a5 += *(const float*)(r0 + e3 + 1024);
            }
            mbar_arrive(cmb_base + 8u * s);
            ++csq;
        }

        const unsigned ob = ((unsigned)(b * C_OUT + co)) * L_DIM + (tx << 9) + tid;
        out[ob]                 = a0;
        out[ob + 256]           = a1;
        out[ob + OSZ]           = a2;
        out[ob + OSZ + 256]     = a3;
        out[ob + 2 * OSZ]       = a4;
        out[ob + 2 * OSZ + 256] = a5;

        // next tile: warp 0 has wn in registers; consumers read the published
        // copy (ordered by the q>=2 tmb acquire after warp-0's q=0 release).
        w = (tid < 32) ? wn : wq[pb ^ 1];
        pb ^= 1;
    }
}

extern "C" void kernel_launch(void* const* d_in, const int* in_sizes, int n_in,
                              void* d_out, int out_size) {
    const float* x   = (const float*)d_in[0];
    const int*   si1 = (const int*)d_in[1];
    const int*   si2 = (const int*)d_in[2];
    const int*   si3 = (const int*)d_in[3];
    float* out = (float*)d_out;

    const int smem_bytes = RING * QBUFB;      // 45696
    cudaFuncSetAttribute(addshift_kernel,
                         cudaFuncAttributeMaxDynamicSharedMemorySize, smem_bytes);

    reset_kernel<<<1, 1>>>();
    addshift_kernel<<<GRID, THREADS, smem_bytes>>>(x, si1, si2, si3, out);
}

// round 16
// speedup vs baseline: 1.0417x; 1.0215x over previous
#include <cuda_runtime.h>
#include <cstdint>

#define B_DIM    8
#define C_OUT    64
#define NK       7
#define GROUP_IN 4
#define C_IN     1792              // 64*4*7
#define L_DIM    4096
#define TILE     512
#define HALO     16                // covers |shift| <= 15
#define ROWW     (TILE + 2*HALO)   // 544 floats per staged row
#define ROWB     (ROWW * 4)        // 2176 bytes per staged row
#define NCH      (GROUP_IN * NK)   // 28 channels per c_out
#define QROWS    7                 // rows per quarter slot
#define QBUFB    (QROWS * ROWB)    // 15232 bytes per quarter slot
#define RING     3
#define THREADS  256
#define CTAS_SM  4
#define GRID     (152 * CTAS_SM)   // 608 persistent CTAs
#define NTILES   (B_DIM * C_OUT * (L_DIM / TILE))   // 4096
#define PERIOD   (NTILES + GRID)   // exact tickets consumed per launch: 4704

// Monotonic ticket counter (zero-initialized device global). Each launch
// consumes EXACTLY PERIOD tickets: GRID initial fetches + one fetch per
// consumed tile (NTILES) -- every CTA's last fetch maps >= NTILES and stops
// it. So w = ticket % PERIOD is a clean per-launch tile id; no reset needed.
__device__ unsigned long long g_ctr;

// --- TMA bulk 1D: global -> shared, mbarrier transaction-counted ---
__device__ __forceinline__ void bulk_g2s(uint32_t dst, const void* src,
                                         unsigned bytes, uint32_t mbar) {
    asm volatile(
        "cp.async.bulk.shared::cluster.global.mbarrier::complete_tx::bytes "
        "[%0], [%1], %2, [%3];"
        :: "r"(dst), "l"(src), "r"(bytes), "r"(mbar) : "memory");
}
__device__ __forceinline__ void mbar_init(uint32_t mbar, unsigned cnt) {
    asm volatile("mbarrier.init.shared.b64 [%0], %1;" :: "r"(mbar), "r"(cnt) : "memory");
}
__device__ __forceinline__ void mbar_arrive_expect(uint32_t mbar, unsigned bytes) {
    asm volatile("mbarrier.arrive.expect_tx.shared.b64 _, [%0], %1;"
                 :: "r"(mbar), "r"(bytes) : "memory");
}
__device__ __forceinline__ void mbar_arrive(uint32_t mbar) {
    asm volatile("mbarrier.arrive.shared.b64 _, [%0];" :: "r"(mbar) : "memory");
}
__device__ __forceinline__ void mbar_wait(uint32_t mbar, unsigned ph) {
    asm volatile(
        "{\n\t.reg .pred P;\n\t"
        "LAB_%=:\n\t"
        "mbarrier.try_wait.parity.acquire.cta.shared::cta.b64 P, [%0], %1, 0x989680;\n\t"
        "@P bra.uni DONE_%=;\n\t"
        "bra.uni LAB_%=;\n\t"
        "DONE_%=:\n\t}"
        :: "r"(mbar), "r"(ph) : "memory");
}

__device__ __forceinline__ int next_ticket() {
    unsigned long long t = atomicAdd(&g_ctr, 1ULL);
    return (int)(t % (unsigned long long)PERIOD);
}

__global__ __launch_bounds__(THREADS, CTAS_SM) void addshift_kernel(
    const float* __restrict__ x,
    const int*   __restrict__ si1,
    const int*   __restrict__ si2,
    const int*   __restrict__ si3,
    float*       __restrict__ out)
{
    extern __shared__ float sm[];                 // ring of 3 quarter-buffers
    __shared__ unsigned tab[C_OUT * NCH];         // packed per-(co,lc) offsets
    __shared__ int wq[2];                         // next-tile id, parity buffered
    __shared__ int w0_s;
    __shared__ __align__(8) unsigned long long mbar_s[2 * RING]; // tmb[3], cmb[3]

    const int tid = threadIdx.x;
    const uint32_t sm_base  = (uint32_t)__cvta_generic_to_shared(sm);
    const uint32_t tmb_base = (uint32_t)__cvta_generic_to_shared(&mbar_s[0]);
    const uint32_t cmb_base = (uint32_t)__cvta_generic_to_shared(&mbar_s[RING]);

    // ---- stage quarter q of tile w_ into ring slot s (warp 0 only) ----
    // staged-row channel offset is closed-form: lane r of quarter q holds
    // global channel (q*448 + r) relative to co*7, i.e. crel=(q*448+r)*L_DIM.
    auto stage = [&](int w_, int q, unsigned s) {
        const int b   = w_ >> 9;
        const int rem = w_ & 511;
        const int co  = rem >> 3;
        const int tx  = rem & 7;
        const bool front = (tx == 0);
        const bool back  = (tx == 7);
        const uint32_t slotb = sm_base + s * (unsigned)QBUFB;
        if (front | back) {                        // zero 16-float OOB halo
            uint32_t zb = slotb + (front ? 0u : (unsigned)((TILE + HALO) * 4));
            if (tid < QROWS * 4) {                 // 28 float4 chunks
                uint32_t a = zb + (unsigned)(tid >> 2) * ROWB
                           + (unsigned)(tid & 3) * 16u;
                asm volatile("st.shared.v4.b32 [%0], {%1,%1,%1,%1};"
                             :: "r"(a), "r"(0) : "memory");
            }
        }
        const unsigned sz = (front | back) ? (ROWB - 64u) : (unsigned)ROWB;
        if (tid == 0) mbar_arrive_expect(tmb_base + 8u * s, QROWS * sz);
        else          mbar_arrive(tmb_base + 8u * s);
        if (tid < QROWS) {
            const int gstart = (tx << 9) - HALO;
            const int crel = (q * 448 + tid) * L_DIM;
            const float* src = x + ((size_t)b * C_IN + (size_t)co * NK) * L_DIM
                             + crel + gstart + (front ? HALO : 0);
            bulk_g2s(slotb + (uint32_t)tid * ROWB + (front ? 64u : 0u), src, sz,
                     tmb_base + 8u * s);
        }
    };

    // ---- prologue: warp 0 inits + stages IMMEDIATELY (no table dependency);
    // warps 1..7 build the offset table concurrently ----
    if (tid < 32) {
        if (tid == 0) {
            #pragma unroll
            for (int s = 0; s < RING; ++s) {
                mbar_init(tmb_base + 8u * s, 32);      // warp-0 lanes
                mbar_init(cmb_base + 8u * s, THREADS); // all consumers
            }
            w0_s = next_ticket();
        }
        __syncwarp();
        const int w0 = w0_s;
        if (w0 < NTILES) { stage(w0, 0, 0u); stage(w0, 1, 1u); }
    }
    // offset table: in-row byte offset = (1 + 5*(idx%7))*4, three 8-bit fields
    for (int c = tid; c < C_IN; c += THREADS) {
        int g  = c / (C_OUT * NK);
        int r  = c - g * (C_OUT * NK);
        int co = r / NK;
        int k  = r - co * NK;
        int lc = g * NK + k;
        unsigned o1 = 4u + 20u * (unsigned)(si1[c] % NK);
        unsigned o2 = 4u + 20u * (unsigned)(si2[c] % NK);
        unsigned o3 = 4u + 20u * (unsigned)(si3[c] % NK);
        tab[co * NCH + lc] = o1 | (o2 << 8) | (o3 << 16);
    }
    __syncthreads();   // tab + mbarrier init visible; last bar.sync in kernel

    int w = w0_s;
    const unsigned OSZ = (unsigned)B_DIM * C_OUT * L_DIM;   // one output tensor

    unsigned stq = 2;                // next stream position to stage (warp 0)
    unsigned csq = 0;                // next stream position to consume
    unsigned tph = 0, cph = 0;       // per-slot phase bits
    int pb = 0;                      // tile parity (for wq buffering)
    const char* smc = (const char*)sm + (unsigned)tid * 4u;

    while (w < NTILES) {
        const int b   = w >> 9;
        const int rem = w & 511;
        const int co  = rem >> 3;
        const int tx  = rem & 7;
        int wn = NTILES;

        float a0 = 0.f, a1 = 0.f, a2 = 0.f, a3 = 0.f, a4 = 0.f, a5 = 0.f;

        #pragma unroll
        for (int q = 0; q < 4; ++q) {
            if (tid < 32) {
                if (q == 0) {
                    // fetch next tile id; publish before this tile's arrives
                    if (tid == 0) { wn = next_ticket(); wq[pb ^ 1] = wn; }
                    wn = __shfl_sync(0xffffffffu, wn, 0);
                }
                // stage stream position stq: quarters 2,3 of w then 0,1 of wn
                const int tgt_w = (q < 2) ? w : wn;
                const int tgt_q = (q < 2) ? (q + 2) : (q - 2);
                if (tgt_w < NTILES) {
                    const unsigned s2 = stq % RING;
                    if (stq >= RING) {
                        mbar_wait(cmb_base + 8u * s2, (cph >> s2) & 1u);
                        cph ^= 1u << s2;
                    }
                    stage(tgt_w, tgt_q, s2);
                }
                ++stq;
            }
            // consume quarter q from slot csq%RING
            const unsigned s = csq % RING;
            mbar_wait(tmb_base + 8u * s, (tph >> s) & 1u); tph ^= 1u << s;
            const unsigned* tp = tab + co * NCH + q * QROWS;
            const char* smb = smc + s * (unsigned)QBUFB;
            #pragma unroll
            for (int j = 0; j < QROWS; ++j) {
                unsigned p = tp[j];                   // one LDS.32 broadcast
                const char* r0 = smb + j * ROWB;
                unsigned e1 = p & 255u;
                unsigned e2 = (p >> 8) & 255u;
                unsigned e3 = p >> 16;
                a0 += *(const float*)(r0 + e1);
                a1 += *(const float*)(r0 + e1 + 1024);
                a2 += *(const float*)(r0 + e2);
                a3 += *(const float*)(r0 + e2 + 1024);
                a4 += *(const float*)(r0 + e3);
                a5 += *(const float*)(r0 + e3 + 1024);
            }
            mbar_arrive(cmb_base + 8u * s);
            ++csq;
        }

        const unsigned ob = ((unsigned)(b * C_OUT + co)) * L_DIM + (tx << 9) + tid;
        out[ob]                 = a0;
        out[ob + 256]           = a1;
        out[ob + OSZ]           = a2;
        out[ob + OSZ + 256]     = a3;
        out[ob + 2 * OSZ]       = a4;
        out[ob + 2 * OSZ + 256] = a5;

        // next tile: warp 0 has wn in registers; consumers read the published
        // copy (ordered by the q>=2 tmb acquire after warp-0's q=0 release).
        w = (tid < 32) ? wn : wq[pb ^ 1];
        pb ^= 1;
    }
}

extern "C" void kernel_launch(void* const* d_in, const int* in_sizes, int n_in,
                              void* d_out, int out_size) {
    const float* x   = (const float*)d_in[0];
    const int*   si1 = (const int*)d_in[1];
    const int*   si2 = (const int*)d_in[2];
    const int*   si3 = (const int*)d_in[3];
    float* out = (float*)d_out;

    const int smem_bytes = RING * QBUFB;      // 45696
    cudaFuncSetAttribute(addshift_kernel,
                         cudaFuncAttributeMaxDynamicSharedMemorySize, smem_bytes);

    addshift_kernel<<<GRID, THREADS, smem_bytes>>>(x, si1, si2, si3, out);
}